// round 1
// baseline (speedup 1.0000x reference)
#include <cuda_runtime.h>
#include <cfloat>
#include <cstdint>

#define B_ROWS 4096
#define KDIM   256
#define MEM    65536
#define VDIM   8
#define SPARS  32
#define NCHUNK 32
#define CHUNK  (MEM/NCHUNK)   // 2048
#define BM     128
#define BN     128
#define KC     32
#define TPB    256
#define AST    132            // padded smem stride for A/B tiles
#define TSTR   134            // padded smem stride for score tile (transposed)

#define SM_FLOATS (2*KC*AST + BN*TSTR + BM*SPARS*2)
#define SMEM_BYTES (SM_FLOATS*4)   // 135168 bytes

// ---- device scratch (allocation-free rule: static __device__ arrays) ----
__device__ float g_cand_val[B_ROWS*NCHUNK*SPARS];  // 16 MB
__device__ int   g_cand_idx[B_ROWS*NCHUNK*SPARS];  // 16 MB
__device__ int   g_topk[B_ROWS*SPARS];
__device__ float g_delta[B_ROWS*VDIM];

__device__ __forceinline__ unsigned long long pack2(float x){
    unsigned long long r;
    asm("mov.b64 %0, {%1, %1};" : "=l"(r) : "r"(__float_as_uint(x)));
    return r;
}
__device__ __forceinline__ void fma2(unsigned long long &c,
                                     unsigned long long a,
                                     unsigned long long b){
    asm("fma.rn.f32x2 %0, %1, %2, %0;" : "+l"(c) : "l"(a), "l"(b));
}

// ============================================================
// K1: scores GEMM (keys @ proj^T) + streaming per-chunk top-32
// grid: (B_ROWS/BM, NCHUNK), block: 256
// ============================================================
__global__ __launch_bounds__(TPB,1)
void k_scores(const float* __restrict__ keys, const float* __restrict__ proj){
    extern __shared__ float sm[];
    float* As  = sm;                       // [KC][AST]
    float* Bs  = sm + KC*AST;              // [KC][AST]
    float* tT  = sm + 2*KC*AST;            // [BN][TSTR]  scores transposed [col][row]
    float* shv = sm + 2*KC*AST + BN*TSTR;  // [BM][32] heap values
    int*   shi = (int*)(shv + BM*SPARS);   // [BM][32] heap indices

    const int tid  = threadIdx.x;
    const int lane = tid & 31;
    const int w    = tid >> 5;
    const int tx   = tid & 15;
    const int ty   = tid >> 4;
    const int row0 = blockIdx.x * BM;
    const int ch0  = blockIdx.y * CHUNK;

    for(int i=tid; i<BM*SPARS; i+=TPB){ shv[i] = -FLT_MAX; shi[i] = 0; }
    __syncthreads();

    for(int ct=0; ct<CHUNK/BN; ct++){
        const int col0 = ch0 + ct*BN;

        unsigned long long acc[4][8];
        #pragma unroll
        for(int rp=0; rp<4; rp++)
            #pragma unroll
            for(int c=0; c<8; c++) acc[rp][c] = 0ull;

        // prefetch first K-chunk into registers
        float4 pA[4], pB[4];
        #pragma unroll
        for(int i=0;i<4;i++){
            int lin=i*TPB+tid; int f4=lin&7; int r=lin>>3;
            pA[i]=*(const float4*)(keys + (size_t)(row0+r)*KDIM + f4*4);
            pB[i]=*(const float4*)(proj + (size_t)(col0+r)*KDIM + f4*4);
        }

        for(int kci=0; kci<KDIM/KC; kci++){
            __syncthreads();
            // store prefetched chunk transposed into smem
            #pragma unroll
            for(int i=0;i<4;i++){
                int lin=i*TPB+tid; int f4=lin&7; int r=lin>>3; int kb=f4*4;
                As[(kb+0)*AST+r]=pA[i].x; As[(kb+1)*AST+r]=pA[i].y;
                As[(kb+2)*AST+r]=pA[i].z; As[(kb+3)*AST+r]=pA[i].w;
                Bs[(kb+0)*AST+r]=pB[i].x; Bs[(kb+1)*AST+r]=pB[i].y;
                Bs[(kb+2)*AST+r]=pB[i].z; Bs[(kb+3)*AST+r]=pB[i].w;
            }
            __syncthreads();
            // prefetch next K-chunk (hidden under compute)
            if(kci+1 < KDIM/KC){
                int kc=(kci+1)*KC;
                #pragma unroll
                for(int i=0;i<4;i++){
                    int lin=i*TPB+tid; int f4=lin&7; int r=lin>>3;
                    pA[i]=*(const float4*)(keys + (size_t)(row0+r)*KDIM + kc + f4*4);
                    pB[i]=*(const float4*)(proj + (size_t)(col0+r)*KDIM + kc + f4*4);
                }
            }
            // packed-f32x2 FMA mainloop
            #pragma unroll 8
            for(int k=0;k<KC;k++){
                const float* ap = As + k*AST + ty*8;
                ulonglong2 aL = *(const ulonglong2*)ap;
                ulonglong2 aH = *(const ulonglong2*)(ap+4);
                unsigned long long a2[4] = {aL.x, aL.y, aH.x, aH.y};
                const float* bp = Bs + k*AST + tx*8;
                float4 b0 = *(const float4*)bp;
                float4 b1 = *(const float4*)(bp+4);
                unsigned long long bb[8] = {pack2(b0.x),pack2(b0.y),pack2(b0.z),pack2(b0.w),
                                            pack2(b1.x),pack2(b1.y),pack2(b1.z),pack2(b1.w)};
                #pragma unroll
                for(int rp=0; rp<4; rp++)
                    #pragma unroll
                    for(int c=0; c<8; c++) fma2(acc[rp][c], a2[rp], bb[c]);
            }
        }

        // stage tile scores (transposed, row pairs packed) to smem
        #pragma unroll
        for(int rp=0; rp<4; rp++)
            #pragma unroll
            for(int c=0; c<8; c++)
                *(unsigned long long*)&tT[(size_t)(tx*8+c)*TSTR + ty*8 + rp*2] = acc[rp][c];
        __syncthreads();

        // per-row streaming top-32: warp w owns rows [w*16, w*16+16)
        for(int r16=0; r16<16; r16++){
            int r = w*16 + r16;
            float hv_l = shv[r*SPARS + lane];
            int   hi_l = shi[r*SPARS + lane];
            float th = hv_l;
            #pragma unroll
            for(int off=16; off; off>>=1)
                th = fminf(th, __shfl_xor_sync(0xffffffffu, th, off));
            for(int g=0; g<BN/32; g++){
                float val = tT[(size_t)(g*32+lane)*TSTR + r];
                unsigned mask = __ballot_sync(0xffffffffu, val > th);
                while(mask){
                    int src = __ffs(mask)-1; mask &= mask-1;
                    float cv = __shfl_sync(0xffffffffu, val, src);
                    if(cv > th){
                        int cc = col0 + g*32 + src;
                        // warp argmin over heap slots
                        float m = hv_l; int ml = lane;
                        #pragma unroll
                        for(int off=16; off; off>>=1){
                            float om = __shfl_xor_sync(0xffffffffu, m, off);
                            int   ol = __shfl_xor_sync(0xffffffffu, ml, off);
                            if(om < m || (om == m && ol < ml)){ m = om; ml = ol; }
                        }
                        if(lane == ml){ hv_l = cv; hi_l = cc; }
                        float m2 = hv_l;
                        #pragma unroll
                        for(int off=16; off; off>>=1)
                            m2 = fminf(m2, __shfl_xor_sync(0xffffffffu, m2, off));
                        th = m2;
                    }
                }
            }
            shv[r*SPARS + lane] = hv_l;
            shi[r*SPARS + lane] = hi_l;
        }
        __syncthreads();
    }

    // emit per-chunk candidates
    for(int r16=0; r16<16; r16++){
        int r = w*16 + r16;
        size_t o = (size_t)(row0+r)*(NCHUNK*SPARS) + (size_t)blockIdx.y*SPARS + lane;
        g_cand_val[o] = shv[r*SPARS + lane];
        g_cand_idx[o] = shi[r*SPARS + lane];
    }
}

// ============================================================
// K2: merge 32 chunk-candidate lists -> final top-32, retrieved, delta
// grid: B_ROWS, block: 256
// ============================================================
__global__ void k_merge(const float* __restrict__ targets,
                        const float* __restrict__ memv,
                        float* __restrict__ out){
    __shared__ float sv[TPB];
    __shared__ int   se[TPB];
    __shared__ int   stop[SPARS];
    __shared__ float racc[VDIM];

    const int tid = threadIdx.x;
    const int row = blockIdx.x;
    const size_t base = (size_t)row * (NCHUNK*SPARS);

    float v[4]; int ix[4];
    #pragma unroll
    for(int j=0;j<4;j++){
        v[j]  = g_cand_val[base + j*TPB + tid];
        ix[j] = g_cand_idx[base + j*TPB + tid];
    }

    for(int it=0; it<SPARS; it++){
        float mv = -FLT_MAX; int mj = 0;
        #pragma unroll
        for(int j=0;j<4;j++) if(v[j] > mv){ mv = v[j]; mj = j; }
        sv[tid] = mv; se[tid] = (mj<<8) | tid;
        __syncthreads();
        for(int s=TPB/2; s>0; s>>=1){
            if(tid < s && sv[tid+s] > sv[tid]){ sv[tid]=sv[tid+s]; se[tid]=se[tid+s]; }
            __syncthreads();
        }
        int win = se[0];
        if(tid == (win & 255)){
            int j = win >> 8;
            int mi = ix[j];
            stop[it] = mi;
            g_topk[row*SPARS + it] = mi;
            v[j] = -FLT_MAX;
        }
        __syncthreads();
    }

    // retrieved = sum_s mem_value[topk[s]]
    if(tid < VDIM) racc[tid] = 0.f;
    __syncthreads();
    {
        int s = tid >> 3, vc = tid & 7;   // 256 threads = 32 s * 8 v
        atomicAdd(&racc[vc], memv[(size_t)stop[s]*VDIM + vc]);
    }
    __syncthreads();
    if(tid < VDIM){
        float r = racc[tid];
        out[(size_t)row*VDIM + tid] = r;
        g_delta[row*VDIM + tid] = (targets[(size_t)row*VDIM + tid] - r) * (0.1f/32.0f);
    }
}

// ============================================================
// K3: copy mem_value into output memory region
// ============================================================
__global__ void k_copy(const float* __restrict__ memv, float* __restrict__ out){
    int i = blockIdx.x*blockDim.x + threadIdx.x;   // < MEM*VDIM/4 = 131072
    ((float4*)out)[B_ROWS*VDIM/4 + i] = ((const float4*)memv)[i];
}

// ============================================================
// K4: scatter-add deltas into output memory region
// ============================================================
__global__ void k_scatter(float* __restrict__ out){
    int g = blockIdx.x*blockDim.x + threadIdx.x;   // < B_ROWS*SPARS
    int b = g >> 5;
    int idx = g_topk[g];
    float* dst = out + (size_t)(B_ROWS + idx)*VDIM;
    const float* d = &g_delta[b*VDIM];
    #pragma unroll
    for(int vv=0; vv<VDIM; vv++) atomicAdd(dst+vv, d[vv]);
}

// ============================================================
extern "C" void kernel_launch(void* const* d_in, const int* in_sizes, int n_in,
                              void* d_out, int out_size){
    const float* keys    = (const float*)d_in[0];
    const float* targets = (const float*)d_in[1];
    const float* proj    = (const float*)d_in[2];
    const float* memv    = (const float*)d_in[3];
    float* out = (float*)d_out;

    cudaFuncSetAttribute(k_scores, cudaFuncAttributeMaxDynamicSharedMemorySize, SMEM_BYTES);

    k_copy  <<<(MEM*VDIM/4)/TPB, TPB>>>(memv, out);
    k_scores<<<dim3(B_ROWS/BM, NCHUNK), TPB, SMEM_BYTES>>>(keys, proj);
    k_merge <<<B_ROWS, TPB>>>(targets, memv, out);
    k_scatter<<<(B_ROWS*SPARS)/TPB, TPB>>>(out);
}